// round 1
// baseline (speedup 1.0000x reference)
#include <cuda_runtime.h>
#include <cstdint>

namespace {

constexpr int Bz  = 4;
constexpr int NHn = 4;
constexpr int Tn  = 512;
constexpr int Dn  = 256;
constexpr int Nn  = 8192;
constexpr int BHn = Bz * NHn;
constexpr float SCALEF = 0.011048543456039806f;  // N^-0.5

// Scratch (device globals: allocation-free per harness rules)
__device__ float g_qr[(size_t)BHn * Tn * Nn];   // 256 MB: RoPE'd Q
__device__ float g_sc[(size_t)BHn * Tn * Tn];   // 16 MB: masked scores

// ---------------------------------------------------------------------------
// K1: RoPE.  qr[2i] = q[2i]*c[2i] - q[2i+1]*s[2i]
//            qr[2i+1] = q[2i+1]*c[2i+1] + q[2i]*s[2i+1]
// ---------------------------------------------------------------------------
__global__ void rope_kernel(const float* __restrict__ Q,
                            const float* __restrict__ C,
                            const float* __restrict__ S) {
    constexpr int PR = Nn / 2;
    size_t tid = (size_t)blockIdx.x * blockDim.x + threadIdx.x;  // pair index
    int t  = (int)((tid / PR) % Tn);
    int n2 = (int)(tid % PR);
    float2 q = reinterpret_cast<const float2*>(Q)[tid];
    float2 c = reinterpret_cast<const float2*>(C)[(size_t)t * PR + n2];
    float2 s = reinterpret_cast<const float2*>(S)[(size_t)t * PR + n2];
    float2 r;
    r.x = q.x * c.x - q.y * s.x;
    r.y = q.y * c.y + q.x * s.y;
    reinterpret_cast<float2*>(g_qr)[tid] = r;
}

// ---------------------------------------------------------------------------
// K2: scores[t,s] = SCALE * dot(QR[t,:], QR[s,:]) for s < t, else 0.
// NT sgemm, BM=BN=64, BK=16, 256 threads, 4x4 microtile.
// Strictly-upper 64x64 tiles are written as zeros without compute.
// ---------------------------------------------------------------------------
__global__ void scores_kernel() {
    const int bh = blockIdx.z;
    const int tb = blockIdx.y;   // row (t) tile
    const int sb = blockIdx.x;   // col (s) tile
    float* Sc = g_sc + (size_t)bh * Tn * Tn;
    const int t0 = tb * 64, s0 = sb * 64;

    if (sb > tb) {  // strictly upper tile: zero fill
        for (int i = threadIdx.x; i < 64 * 64; i += 256)
            Sc[(size_t)(t0 + i / 64) * Tn + s0 + (i % 64)] = 0.f;
        return;
    }

    const float* A = g_qr + (size_t)bh * Tn * Nn;
    __shared__ float As[16][68];
    __shared__ float Bs[16][68];
    const int tx = threadIdx.x % 16, ty = threadIdx.x / 16;
    const int lr = threadIdx.x / 4;
    const int lc = (threadIdx.x % 4) * 4;
    float acc[4][4] = {};

    for (int k0 = 0; k0 < Nn; k0 += 16) {
        float4 a = *reinterpret_cast<const float4*>(&A[(size_t)(t0 + lr) * Nn + k0 + lc]);
        float4 b = *reinterpret_cast<const float4*>(&A[(size_t)(s0 + lr) * Nn + k0 + lc]);
        As[lc + 0][lr] = a.x; As[lc + 1][lr] = a.y; As[lc + 2][lr] = a.z; As[lc + 3][lr] = a.w;
        Bs[lc + 0][lr] = b.x; Bs[lc + 1][lr] = b.y; Bs[lc + 2][lr] = b.z; Bs[lc + 3][lr] = b.w;
        __syncthreads();
#pragma unroll
        for (int kk = 0; kk < 16; kk++) {
            float4 am = *reinterpret_cast<const float4*>(&As[kk][ty * 4]);
            float4 bn = *reinterpret_cast<const float4*>(&Bs[kk][tx * 4]);
            float amv[4] = {am.x, am.y, am.z, am.w};
            float bnv[4] = {bn.x, bn.y, bn.z, bn.w};
#pragma unroll
            for (int i = 0; i < 4; i++)
#pragma unroll
                for (int j = 0; j < 4; j++)
                    acc[i][j] += amv[i] * bnv[j];
        }
        __syncthreads();
    }

#pragma unroll
    for (int i = 0; i < 4; i++) {
        int t = t0 + ty * 4 + i;
#pragma unroll
        for (int j = 0; j < 4; j++) {
            int s = s0 + tx * 4 + j;
            Sc[(size_t)t * Tn + s] = (s < t) ? acc[i][j] * SCALEF : 0.f;
        }
    }
}

// ---------------------------------------------------------------------------
// K3: out[t,d] = sum_s scores[t,s]*V[s,d] + sum_n QR[t,n]*state[n,d]
// NN sgemm, two accumulation phases into the same 4x4 microtile.
// ---------------------------------------------------------------------------
__global__ void out_kernel(const float* __restrict__ V,
                           const float* __restrict__ state,
                           float* __restrict__ out) {
    const int bh = blockIdx.z, b = bh / NHn;
    const int t0 = blockIdx.y * 64, d0 = blockIdx.x * 64;
    const float* Sc  = g_sc + (size_t)bh * Tn * Tn;
    const float* QRh = g_qr + (size_t)bh * Tn * Nn;
    const float* Vb  = V + (size_t)b * Tn * Dn;
    const float* St  = state + (size_t)bh * Nn * Dn;

    __shared__ float As[16][68];
    __shared__ float Bs[16][68];
    const int tx = threadIdx.x % 16, ty = threadIdx.x / 16;
    const int lrA = threadIdx.x / 4,  lcA = (threadIdx.x % 4) * 4;
    const int lrB = threadIdx.x / 16, lcB = (threadIdx.x % 16) * 4;
    float acc[4][4] = {};

    // phase 1: scores @ V   (A stride Tn, K = Tn)
    for (int k0 = 0; k0 < Tn; k0 += 16) {
        float4 a  = *reinterpret_cast<const float4*>(&Sc[(size_t)(t0 + lrA) * Tn + k0 + lcA]);
        float4 bb = *reinterpret_cast<const float4*>(&Vb[(size_t)(k0 + lrB) * Dn + d0 + lcB]);
        As[lcA + 0][lrA] = a.x; As[lcA + 1][lrA] = a.y; As[lcA + 2][lrA] = a.z; As[lcA + 3][lrA] = a.w;
        *reinterpret_cast<float4*>(&Bs[lrB][lcB]) = bb;
        __syncthreads();
#pragma unroll
        for (int kk = 0; kk < 16; kk++) {
            float4 am = *reinterpret_cast<const float4*>(&As[kk][ty * 4]);
            float4 bn = *reinterpret_cast<const float4*>(&Bs[kk][tx * 4]);
            float amv[4] = {am.x, am.y, am.z, am.w};
            float bnv[4] = {bn.x, bn.y, bn.z, bn.w};
#pragma unroll
            for (int i = 0; i < 4; i++)
#pragma unroll
                for (int j = 0; j < 4; j++)
                    acc[i][j] += amv[i] * bnv[j];
        }
        __syncthreads();
    }

    // phase 2: QR @ state   (A stride Nn, K = Nn)
    for (int k0 = 0; k0 < Nn; k0 += 16) {
        float4 a  = *reinterpret_cast<const float4*>(&QRh[(size_t)(t0 + lrA) * Nn + k0 + lcA]);
        float4 bb = *reinterpret_cast<const float4*>(&St[(size_t)(k0 + lrB) * Dn + d0 + lcB]);
        As[lcA + 0][lrA] = a.x; As[lcA + 1][lrA] = a.y; As[lcA + 2][lrA] = a.z; As[lcA + 3][lrA] = a.w;
        *reinterpret_cast<float4*>(&Bs[lrB][lcB]) = bb;
        __syncthreads();
#pragma unroll
        for (int kk = 0; kk < 16; kk++) {
            float4 am = *reinterpret_cast<const float4*>(&As[kk][ty * 4]);
            float4 bn = *reinterpret_cast<const float4*>(&Bs[kk][tx * 4]);
            float amv[4] = {am.x, am.y, am.z, am.w};
            float bnv[4] = {bn.x, bn.y, bn.z, bn.w};
#pragma unroll
            for (int i = 0; i < 4; i++)
#pragma unroll
                for (int j = 0; j < 4; j++)
                    acc[i][j] += amv[i] * bnv[j];
        }
        __syncthreads();
    }

    float* O = out + (size_t)bh * Tn * Dn;
#pragma unroll
    for (int i = 0; i < 4; i++) {
        int t = t0 + ty * 4 + i;
#pragma unroll
        for (int j = 0; j < 4; j++) {
            int d = d0 + tx * 4 + j;
            O[(size_t)t * Dn + d] = acc[i][j];
        }
    }
}

// ---------------------------------------------------------------------------
// K4: new_state[n,d] = state[n,d] + SCALE * sum_t QR[t,n] * V[t,d]
// TN sgemm (A read column-n contiguous per row -> coalesced direct loads).
// ---------------------------------------------------------------------------
__global__ void nstate_kernel(const float* __restrict__ V,
                              const float* __restrict__ state,
                              float* __restrict__ outns) {
    const int bh = blockIdx.z, b = bh / NHn;
    const int n0 = blockIdx.y * 64, d0 = blockIdx.x * 64;
    const float* QRh = g_qr + (size_t)bh * Tn * Nn;
    const float* Vb  = V + (size_t)b * Tn * Dn;

    __shared__ float As[16][68];
    __shared__ float Bs[16][68];
    const int tx = threadIdx.x % 16, ty = threadIdx.x / 16;
    const int lr = threadIdx.x / 16, lc = (threadIdx.x % 16) * 4;
    float acc[4][4] = {};

    for (int k0 = 0; k0 < Tn; k0 += 16) {
        float4 a  = *reinterpret_cast<const float4*>(&QRh[(size_t)(k0 + lr) * Nn + n0 + lc]);
        float4 bb = *reinterpret_cast<const float4*>(&Vb [(size_t)(k0 + lr) * Dn + d0 + lc]);
        *reinterpret_cast<float4*>(&As[lr][lc]) = a;
        *reinterpret_cast<float4*>(&Bs[lr][lc]) = bb;
        __syncthreads();
#pragma unroll
        for (int kk = 0; kk < 16; kk++) {
            float4 am = *reinterpret_cast<const float4*>(&As[kk][ty * 4]);
            float4 bn = *reinterpret_cast<const float4*>(&Bs[kk][tx * 4]);
            float amv[4] = {am.x, am.y, am.z, am.w};
            float bnv[4] = {bn.x, bn.y, bn.z, bn.w};
#pragma unroll
            for (int i = 0; i < 4; i++)
#pragma unroll
                for (int j = 0; j < 4; j++)
                    acc[i][j] += amv[i] * bnv[j];
        }
        __syncthreads();
    }

    const float* St = state + (size_t)bh * Nn * Dn;
    float* O = outns + (size_t)bh * Nn * Dn;
#pragma unroll
    for (int i = 0; i < 4; i++) {
        int n = n0 + ty * 4 + i;
#pragma unroll
        for (int j = 0; j < 4; j++) {
            int d = d0 + tx * 4 + j;
            O[(size_t)n * Dn + d] = St[(size_t)n * Dn + d] + SCALEF * acc[i][j];
        }
    }
}

}  // namespace

extern "C" void kernel_launch(void* const* d_in, const int* in_sizes, int n_in,
                              void* d_out, int out_size) {
    const float* Q     = (const float*)d_in[0];
    const float* V     = (const float*)d_in[1];
    const float* state = (const float*)d_in[2];
    const float* cosb  = (const float*)d_in[3];
    const float* sinb  = (const float*)d_in[4];
    float* out = (float*)d_out;

    // K1: RoPE(Q) -> g_qr. 33,554,432 pairs.
    rope_kernel<<<(unsigned)((size_t)BHn * Tn * (Nn / 2) / 256), 256>>>(Q, cosb, sinb);

    // K2: masked scores -> g_sc
    scores_kernel<<<dim3(Tn / 64, Tn / 64, BHn), 256>>>();

    // K3: output = scores@V + QR@state
    out_kernel<<<dim3(Dn / 64, Tn / 64, BHn), 256>>>(V, state, out);

    // K4: new_state = state + SCALE * QR^T @ V  (written after output block)
    nstate_kernel<<<dim3(Dn / 64, Nn / 64, BHn), 256>>>(
        V, state, out + (size_t)BHn * Tn * Dn);
}

// round 5
// speedup vs baseline: 1.6683x; 1.6683x over previous
#include <cuda_runtime.h>
#include <cstdint>

namespace {

constexpr int Bz  = 4;
constexpr int NHn = 4;
constexpr int Tn  = 512;
constexpr int Dn  = 256;
constexpr int Nn  = 8192;
constexpr int BHn = Bz * NHn;
constexpr float SCALEF = 0.011048543456039806f;  // N^-0.5

// Scratch (device globals; allocation-free per harness rules)
__device__ float g_qr[(size_t)BHn * Tn * Nn];   // 256 MB RoPE'd Q  (t,n)
__device__ float g_sc[(size_t)BHn * Tn * Tn];   // 16 MB masked scores (t,s)

// ---------------------------------------------------------------------------
// Tiling
// ---------------------------------------------------------------------------
constexpr int BM = 128, BN = 128, BK = 32;
constexpr int ASTR = BK + 4;    // 36 floats: A row stride (conflict-free frags)
constexpr int BSTR = BN + 8;    // 136 floats: B row stride (conflict-free frags)
constexpr int ASZ = BM * ASTR;  // 4608 floats
constexpr int BSZ = BK * BSTR;  // 4352 floats
constexpr int SMEM_TOTAL = 2 * (ASZ + BSZ) * 4;  // 71680 B

__device__ __forceinline__ uint32_t f2tf32(float x) {
    uint32_t u;
    asm("cvt.rna.tf32.f32 %0, %1;" : "=r"(u) : "f"(x));
    return u;
}

__device__ __forceinline__ void mma_tf32(float c[4], const uint32_t a[4],
                                         const uint32_t b[2]) {
    asm volatile(
        "mma.sync.aligned.m16n8k8.row.col.f32.tf32.tf32.f32 "
        "{%0,%1,%2,%3}, {%4,%5,%6,%7}, {%8,%9}, {%0,%1,%2,%3};"
        : "+f"(c[0]), "+f"(c[1]), "+f"(c[2]), "+f"(c[3])
        : "r"(a[0]), "r"(a[1]), "r"(a[2]), "r"(a[3]), "r"(b[0]), "r"(b[1]));
}

// Compute one k-octet (k8) of the 64x32 warp tile from SMEM.
__device__ __forceinline__ void mma_octet(const float* __restrict__ As,
                                          const float* __restrict__ Bs,
                                          int ko, int wm, int wn,
                                          int gid, int tig, float c[16][4]) {
    uint32_t a[4][4], b[4][2];
#pragma unroll
    for (int im = 0; im < 4; ++im) {
        const float* pa = As + (wm + im * 16 + gid) * ASTR + ko + tig;
        a[im][0] = f2tf32(pa[0]);
        a[im][1] = f2tf32(pa[8 * ASTR]);
        a[im][2] = f2tf32(pa[4]);
        a[im][3] = f2tf32(pa[8 * ASTR + 4]);
    }
#pragma unroll
    for (int jn = 0; jn < 4; ++jn) {
        const float* pb = Bs + (ko + tig) * BSTR + wn + jn * 8 + gid;
        b[jn][0] = f2tf32(pb[0]);
        b[jn][1] = f2tf32(pb[4 * BSTR]);
    }
#pragma unroll
    for (int im = 0; im < 4; ++im)
#pragma unroll
        for (int jn = 0; jn < 4; ++jn)
            mma_tf32(c[im * 4 + jn], a[im], b[jn]);
}

// ---------------------------------------------------------------------------
// Staging: global -> regs, regs -> smem  (double-buffered pipeline)
// ---------------------------------------------------------------------------
// A direct: src (m,k) row-major, row stride ld. thread -> 4x float4.
__device__ __forceinline__ void ldA_dir(const float* src, int ld, float4 r[4]) {
    int m = threadIdx.x >> 3, kc = (threadIdx.x & 7) * 4;
#pragma unroll
    for (int i = 0; i < 4; ++i)
        r[i] = *reinterpret_cast<const float4*>(src + (size_t)(m + i * 32) * ld + kc);
}
__device__ __forceinline__ void stA_dir(float* As, const float4 r[4]) {
    int m = threadIdx.x >> 3, kc = (threadIdx.x & 7) * 4;
#pragma unroll
    for (int i = 0; i < 4; ++i)
        *reinterpret_cast<float4*>(As + (m + i * 32) * ASTR + kc) = r[i];
}
// A transposed: src (k,m) row-major (ld along m). As[m][k].
__device__ __forceinline__ void ldA_tr(const float* src, int ld, float4 r[4]) {
    int k = threadIdx.x >> 5, mc = (threadIdx.x & 31) * 4;
#pragma unroll
    for (int i = 0; i < 4; ++i)
        r[i] = *reinterpret_cast<const float4*>(src + (size_t)(k + i * 8) * ld + mc);
}
__device__ __forceinline__ void stA_tr(float* As, const float4 r[4]) {
    int k = threadIdx.x >> 5, mc = (threadIdx.x & 31) * 4;
#pragma unroll
    for (int i = 0; i < 4; ++i) {
        int kk = k + i * 8;
        As[(mc + 0) * ASTR + kk] = r[i].x;
        As[(mc + 1) * ASTR + kk] = r[i].y;
        As[(mc + 2) * ASTR + kk] = r[i].z;
        As[(mc + 3) * ASTR + kk] = r[i].w;
    }
}
// B direct: src (k,n) row-major. Bs[k][n].
__device__ __forceinline__ void ldB_dir(const float* src, int ld, float4 r[4]) {
    int k = threadIdx.x >> 5, nc = (threadIdx.x & 31) * 4;
#pragma unroll
    for (int i = 0; i < 4; ++i)
        r[i] = *reinterpret_cast<const float4*>(src + (size_t)(k + i * 8) * ld + nc);
}
__device__ __forceinline__ void stB_dir(float* Bs, const float4 r[4]) {
    int k = threadIdx.x >> 5, nc = (threadIdx.x & 31) * 4;
#pragma unroll
    for (int i = 0; i < 4; ++i)
        *reinterpret_cast<float4*>(Bs + (k + i * 8) * BSTR + nc) = r[i];
}
// B transposed: src (n,k) row-major. Bs[k][n].
__device__ __forceinline__ void ldB_tr(const float* src, int ld, float4 r[4]) {
    int n = threadIdx.x >> 3, kc = (threadIdx.x & 7) * 4;
#pragma unroll
    for (int i = 0; i < 4; ++i)
        r[i] = *reinterpret_cast<const float4*>(src + (size_t)(n + i * 32) * ld + kc);
}
__device__ __forceinline__ void stB_tr(float* Bs, const float4 r[4]) {
    int n = threadIdx.x >> 3, kc = (threadIdx.x & 7) * 4;
#pragma unroll
    for (int i = 0; i < 4; ++i) {
        int nn = n + i * 32;
        Bs[(kc + 0) * BSTR + nn] = r[i].x;
        Bs[(kc + 1) * BSTR + nn] = r[i].y;
        Bs[(kc + 2) * BSTR + nn] = r[i].z;
        Bs[(kc + 3) * BSTR + nn] = r[i].w;
    }
}

// ---------------------------------------------------------------------------
// K1: RoPE -> g_qr (fp32)
// ---------------------------------------------------------------------------
__global__ void rope_kernel(const float* __restrict__ Q,
                            const float* __restrict__ C,
                            const float* __restrict__ S) {
    constexpr int PR = Nn / 2;
    size_t tid = (size_t)blockIdx.x * blockDim.x + threadIdx.x;  // pair index
    int t  = (int)((tid / PR) % Tn);
    int n2 = (int)(tid % PR);
    float2 q = reinterpret_cast<const float2*>(Q)[tid];
    float2 c = reinterpret_cast<const float2*>(C)[(size_t)t * PR + n2];
    float2 s = reinterpret_cast<const float2*>(S)[(size_t)t * PR + n2];
    float2 r;
    r.x = q.x * c.x - q.y * s.x;
    r.y = q.y * c.y + q.x * s.y;
    reinterpret_cast<float2*>(g_qr)[tid] = r;
}

// ---------------------------------------------------------------------------
// K2: scores = mask(QR @ QR^T) * SCALE (lower-tri tiles only)
// grid (4, 4, 16): x = s-tile, y = t-tile, z = bh.  Upper tiles: no work
// (never read downstream).
// ---------------------------------------------------------------------------
__global__ void __launch_bounds__(256, 1) scores_gemm() {
    const int sb = blockIdx.x, tb = blockIdx.y, bh = blockIdx.z;
    if (sb > tb) return;
    extern __shared__ float sm[];
    float* As[2] = {sm, sm + ASZ};
    float* Bs[2] = {sm + 2 * ASZ, sm + 2 * ASZ + BSZ};

    const int t0 = tb * BM, s0 = sb * BN;
    const int lane = threadIdx.x & 31, wid = threadIdx.x >> 5;
    const int gid = lane >> 2, tig = lane & 3;
    const int wm = (wid & 1) * 64, wn = (wid >> 1) * 32;
    const float* Asrc = g_qr + ((size_t)bh * Tn + t0) * Nn;
    const float* Bsrc = g_qr + ((size_t)bh * Tn + s0) * Nn;

    float c[16][4] = {};
    constexpr int KT = Nn / BK;  // 256

    float4 ra[4], rb[4];
    ldA_dir(Asrc, Nn, ra); ldB_tr(Bsrc, Nn, rb);
    stA_dir(As[0], ra);    stB_tr(Bs[0], rb);
    __syncthreads();

    int cur = 0;
    for (int kt = 0; kt < KT; ++kt) {
        bool nxt = kt + 1 < KT;
        if (nxt) {
            ldA_dir(Asrc + (kt + 1) * BK, Nn, ra);
            ldB_tr (Bsrc + (kt + 1) * BK, Nn, rb);
        }
#pragma unroll
        for (int ko = 0; ko < BK; ko += 8)
            mma_octet(As[cur], Bs[cur], ko, wm, wn, gid, tig, c);
        if (nxt) { stA_dir(As[cur ^ 1], ra); stB_tr(Bs[cur ^ 1], rb); }
        __syncthreads();
        cur ^= 1;
    }

    float* Sc = g_sc + (size_t)bh * Tn * Tn;
#pragma unroll
    for (int im = 0; im < 4; ++im)
#pragma unroll
        for (int jn = 0; jn < 4; ++jn) {
            int t = t0 + wm + im * 16 + gid;
            int s = s0 + wn + jn * 8 + tig * 2;
            float* cc = c[im * 4 + jn];
            Sc[(size_t)t * Tn + s]           = (s     < t) ? cc[0] * SCALEF : 0.f;
            Sc[(size_t)t * Tn + s + 1]       = (s + 1 < t) ? cc[1] * SCALEF : 0.f;
            Sc[(size_t)(t + 8) * Tn + s]     = (s     < t + 8) ? cc[2] * SCALEF : 0.f;
            Sc[(size_t)(t + 8) * Tn + s + 1] = (s + 1 < t + 8) ? cc[3] * SCALEF : 0.f;
        }
}

// ---------------------------------------------------------------------------
// K3: out = scores @ V + QR @ state  (two K-segments, one accumulator)
// grid (2, 4, 16): x = d-tile, y = t-tile, z = bh
// ---------------------------------------------------------------------------
__global__ void __launch_bounds__(256, 1) out_gemm(const float* __restrict__ V,
                                                   const float* __restrict__ state,
                                                   float* __restrict__ out) {
    extern __shared__ float sm[];
    float* As[2] = {sm, sm + ASZ};
    float* Bs[2] = {sm + 2 * ASZ, sm + 2 * ASZ + BSZ};

    const int db = blockIdx.x, tb = blockIdx.y, bh = blockIdx.z, b = bh >> 2;
    const int t0 = tb * BM, d0 = db * BN;
    const int lane = threadIdx.x & 31, wid = threadIdx.x >> 5;
    const int gid = lane >> 2, tig = lane & 3;
    const int wm = (wid & 1) * 64, wn = (wid >> 1) * 32;

    const float* A1 = g_sc + ((size_t)bh * Tn + t0) * Tn;          // (t,s) ld T
    const float* B1 = V + (size_t)b * Tn * Dn + d0;                // (s,d) ld D
    const float* A2 = g_qr + ((size_t)bh * Tn + t0) * Nn;          // (t,n) ld N
    const float* B2 = state + (size_t)bh * Nn * Dn + d0;           // (n,d) ld D

    const int KT1 = (tb + 1) * (BM / BK);   // causal trim: s < (tb+1)*128
    const int KT2 = Nn / BK;
    const int KT = KT1 + KT2;

    float c[16][4] = {};
    float4 ra[4], rb[4];

    auto ld_iter = [&](int kt, float4 a[4], float4 bbr[4]) {
        if (kt < KT1) {
            ldA_dir(A1 + kt * BK, Tn, a);
            ldB_dir(B1 + (size_t)kt * BK * Dn, Dn, bbr);
        } else {
            int k2 = kt - KT1;
            ldA_dir(A2 + k2 * BK, Nn, a);
            ldB_dir(B2 + (size_t)k2 * BK * Dn, Dn, bbr);
        }
    };

    ld_iter(0, ra, rb);
    stA_dir(As[0], ra); stB_dir(Bs[0], rb);
    __syncthreads();

    int cur = 0;
    for (int kt = 0; kt < KT; ++kt) {
        bool nxt = kt + 1 < KT;
        if (nxt) ld_iter(kt + 1, ra, rb);
#pragma unroll
        for (int ko = 0; ko < BK; ko += 8)
            mma_octet(As[cur], Bs[cur], ko, wm, wn, gid, tig, c);
        if (nxt) { stA_dir(As[cur ^ 1], ra); stB_dir(Bs[cur ^ 1], rb); }
        __syncthreads();
        cur ^= 1;
    }

    float* O = out + ((size_t)bh * Tn + t0) * Dn + d0;
#pragma unroll
    for (int im = 0; im < 4; ++im)
#pragma unroll
        for (int jn = 0; jn < 4; ++jn) {
            int r = wm + im * 16 + gid;
            int cN = wn + jn * 8 + tig * 2;
            float* cc = c[im * 4 + jn];
            O[(size_t)r * Dn + cN]           = cc[0];
            O[(size_t)r * Dn + cN + 1]       = cc[1];
            O[(size_t)(r + 8) * Dn + cN]     = cc[2];
            O[(size_t)(r + 8) * Dn + cN + 1] = cc[3];
        }
}

// ---------------------------------------------------------------------------
// K4: new_state = state + SCALE * QR^T @ V
// grid (2, 64, 16): x = d-tile, y = n-tile, z = bh
// ---------------------------------------------------------------------------
__global__ void __launch_bounds__(256, 1) nstate_gemm(const float* __restrict__ V,
                                                      const float* __restrict__ state,
                                                      float* __restrict__ outns) {
    extern __shared__ float sm[];
    float* As[2] = {sm, sm + ASZ};
    float* Bs[2] = {sm + 2 * ASZ, sm + 2 * ASZ + BSZ};

    const int db = blockIdx.x, nb = blockIdx.y, bh = blockIdx.z, b = bh >> 2;
    const int n0 = nb * BM, d0 = db * BN;
    const int lane = threadIdx.x & 31, wid = threadIdx.x >> 5;
    const int gid = lane >> 2, tig = lane & 3;
    const int wm = (wid & 1) * 64, wn = (wid >> 1) * 32;

    const float* Asrc = g_qr + (size_t)bh * Tn * Nn + n0;  // (t, n): k rows, m cols
    const float* Bsrc = V + (size_t)b * Tn * Dn + d0;      // (t, d)

    float c[16][4] = {};
    constexpr int KT = Tn / BK;  // 16

    float4 ra[4], rb[4];
    ldA_tr(Asrc, Nn, ra); ldB_dir(Bsrc, Dn, rb);
    stA_tr(As[0], ra);    stB_dir(Bs[0], rb);
    __syncthreads();

    int cur = 0;
    for (int kt = 0; kt < KT; ++kt) {
        bool nxt = kt + 1 < KT;
        if (nxt) {
            ldA_tr (Asrc + (size_t)(kt + 1) * BK * Nn, Nn, ra);
            ldB_dir(Bsrc + (size_t)(kt + 1) * BK * Dn, Dn, rb);
        }
#pragma unroll
        for (int ko = 0; ko < BK; ko += 8)
            mma_octet(As[cur], Bs[cur], ko, wm, wn, gid, tig, c);
        if (nxt) { stA_tr(As[cur ^ 1], ra); stB_dir(Bs[cur ^ 1], rb); }
        __syncthreads();
        cur ^= 1;
    }

    const float* St = state + ((size_t)bh * Nn + n0) * Dn + d0;
    float* O = outns + ((size_t)bh * Nn + n0) * Dn + d0;
#pragma unroll
    for (int im = 0; im < 4; ++im)
#pragma unroll
        for (int jn = 0; jn < 4; ++jn) {
            int r = wm + im * 16 + gid;
            int cN = wn + jn * 8 + tig * 2;
            float* cc = c[im * 4 + jn];
            O[(size_t)r * Dn + cN]           = St[(size_t)r * Dn + cN]           + SCALEF * cc[0];
            O[(size_t)r * Dn + cN + 1]       = St[(size_t)r * Dn + cN + 1]       + SCALEF * cc[1];
            O[(size_t)(r + 8) * Dn + cN]     = St[(size_t)(r + 8) * Dn + cN]     + SCALEF * cc[2];
            O[(size_t)(r + 8) * Dn + cN + 1] = St[(size_t)(r + 8) * Dn + cN + 1] + SCALEF * cc[3];
        }
}

}  // namespace

extern "C" void kernel_launch(void* const* d_in, const int* in_sizes, int n_in,
                              void* d_out, int out_size) {
    const float* Q     = (const float*)d_in[0];
    const float* V     = (const float*)d_in[1];
    const float* state = (const float*)d_in[2];
    const float* cosb  = (const float*)d_in[3];
    const float* sinb  = (const float*)d_in[4];
    float* out = (float*)d_out;

    cudaFuncSetAttribute(scores_gemm, cudaFuncAttributeMaxDynamicSharedMemorySize, SMEM_TOTAL);
    cudaFuncSetAttribute(out_gemm,    cudaFuncAttributeMaxDynamicSharedMemorySize, SMEM_TOTAL);
    cudaFuncSetAttribute(nstate_gemm, cudaFuncAttributeMaxDynamicSharedMemorySize, SMEM_TOTAL);

    rope_kernel<<<(unsigned)((size_t)BHn * Tn * (Nn / 2) / 256), 256>>>(Q, cosb, sinb);
    scores_gemm<<<dim3(4, 4, BHn), 256, SMEM_TOTAL>>>();
    out_gemm<<<dim3(2, 4, BHn), 256, SMEM_TOTAL>>>(V, state, out);
    nstate_gemm<<<dim3(2, Nn / BM, BHn), 256, SMEM_TOTAL>>>(
        V, state, out + (size_t)BHn * Tn * Dn);
}